// round 4
// baseline (speedup 1.0000x reference)
#include <cuda_runtime.h>

#define TDIM 64
#define TILE 128
#define LDA 132   // row-dim stride for XnT / ZhT (k-major), 132*4 % 16 == 0

typedef unsigned long long ull;

__constant__ __align__(16) float cR[4096];    // R[j][k] row-major
__constant__ __align__(16) float cRT[4096];   // RT[k][j] = R[j][k]
__device__ __align__(16) float g_RT[4096];    // scratch for building RT

static __device__ __forceinline__ ull pack2dup(float v) {
    ull r; asm("mov.b64 %0, {%1, %1};" : "=l"(r) : "f"(v)); return r;
}
static __device__ __forceinline__ float2 unpack2(ull v) {
    float2 r; asm("mov.b64 {%0, %1}, %2;" : "=f"(r.x), "=f"(r.y) : "l"(v)); return r;
}
// packed fp32x2 FMA, rn — bit-identical to 2x scalar FFMA
static __device__ __forceinline__ void ffma2(ull& d, ull a, ull b) {
    asm("fma.rn.f32x2 %0, %1, %2, %0;" : "+l"(d) : "l"(a), "l"(b));
}

// branchless 4-step binary search over 15 sorted midpoints -> nearest codebook value
static __device__ __forceinline__ float qlookup(float z, const float* __restrict__ sBnd,
                                                const float* __restrict__ sCb) {
    int idx = (z > sBnd[7]) ? 8 : 0;
    idx += (z > sBnd[idx + 3]) ? 4 : 0;
    idx += (z > sBnd[idx + 1]) ? 2 : 0;
    idx += (z > sBnd[idx]) ? 1 : 0;
    return sCb[idx];
}

__global__ void tq_transpose(const float* __restrict__ Rg) {
    int i = blockIdx.x * blockDim.x + threadIdx.x;   // 4096 threads
    int j = i >> 6, k = i & 63;
    g_RT[k * 64 + j] = Rg[j * 64 + k];
}

__global__ void __launch_bounds__(256, 3)
tq_kernel(const float* __restrict__ x, const float* __restrict__ cb,
          float* __restrict__ out, int nrows)
{
    extern __shared__ float smem[];
    float* sXnT   = smem;                  // [64][LDA] normalized x, k-major; reused as ZhT[j][row]
    float* sScale = sXnT + 64 * LDA;       // [TILE]
    float* sCb    = sScale + TILE;         // [16]
    float* sBnd   = sCb + 16;              // [15]

    const int t    = threadIdx.x;
    const int row0 = blockIdx.x * TILE;

    if (t < 16) sCb[t] = cb[t];
    if (t < 15) sBnd[t] = 0.5f * (cb[t] + cb[t + 1]);

    // ---- load x tile, per-row norm (2 threads per row), write normalized transposed ----
    {
        int r = t >> 1;          // local row 0..127
        int h = t & 1;           // which half of the 64 dims
        long long grow = (long long)row0 + r;
        long long gr = grow < nrows ? grow : (long long)nrows - 1;
        const float4* xp = (const float4*)(x + gr * 64 + h * 32);
        float4 v[8];
        float ss = 0.f;
        #pragma unroll
        for (int i2 = 0; i2 < 8; i2++) {
            v[i2] = xp[i2];
            ss += v[i2].x * v[i2].x + v[i2].y * v[i2].y + v[i2].z * v[i2].z + v[i2].w * v[i2].w;
        }
        ss += __shfl_xor_sync(0xffffffffu, ss, 1);
        float scale = fmaxf(sqrtf(ss), 1e-8f);
        float inv = 1.0f / scale;    // precise division: fp32-accurate z for the argmin
        if (h == 0) sScale[r] = scale;
        #pragma unroll
        for (int i2 = 0; i2 < 8; i2++) {
            int k = h * 32 + i2 * 4;
            sXnT[(k + 0) * LDA + r] = v[i2].x * inv;
            sXnT[(k + 1) * LDA + r] = v[i2].y * inv;
            sXnT[(k + 2) * LDA + r] = v[i2].z * inv;
            sXnT[(k + 3) * LDA + r] = v[i2].w * inv;
        }
    }
    __syncthreads();

    // ---- mapping: warp -> 8 output cols (B address warp-uniform => const-port broadcast),
    //      lane -> 4 rows ----
    const int w  = t >> 5;
    const int l  = t & 31;
    const int ca = 8 * w;        // cols ca..ca+7
    const int ra = 4 * l;        // rows ra..ra+3

    ull acc[4][4];   // [row r][col-pair jp]; f32x2 = cols (ca+2jp, ca+2jp+1)
    #pragma unroll
    for (int a = 0; a < 4; a++)
        #pragma unroll
        for (int b = 0; b < 4; b++) acc[a][b] = 0ull;

    // ---- GEMM1: z[r][j] = sum_k xn[r][k] * R[j][k]  (A = XnT[k][r] smem, B = RT[k][j] const) ----
    #pragma unroll 8
    for (int p = 0; p < 64; ++p) {
        float4 a4 = *(const float4*)(sXnT + p * LDA + ra);            // 4 rows, conflict-free
        ulonglong2 b01 = *(const ulonglong2*)(cRT + p * 64 + ca);     // cols ca..ca+3 (const port)
        ulonglong2 b23 = *(const ulonglong2*)(cRT + p * 64 + ca + 4); // cols ca+4..ca+7
        ull A0 = pack2dup(a4.x);
        ull A1 = pack2dup(a4.y);
        ull A2 = pack2dup(a4.z);
        ull A3 = pack2dup(a4.w);
        ffma2(acc[0][0], A0, b01.x); ffma2(acc[0][1], A0, b01.y); ffma2(acc[0][2], A0, b23.x); ffma2(acc[0][3], A0, b23.y);
        ffma2(acc[1][0], A1, b01.x); ffma2(acc[1][1], A1, b01.y); ffma2(acc[1][2], A1, b23.x); ffma2(acc[1][3], A1, b23.y);
        ffma2(acc[2][0], A2, b01.x); ffma2(acc[2][1], A2, b01.y); ffma2(acc[2][2], A2, b23.x); ffma2(acc[2][3], A2, b23.y);
        ffma2(acc[3][0], A3, b01.x); ffma2(acc[3][1], A3, b01.y); ffma2(acc[3][2], A3, b23.x); ffma2(acc[3][3], A3, b23.y);
    }
    __syncthreads();   // all reads of sXnT done before we overwrite it with ZhT

    // ---- quantize and write z_hat transposed: ZhT[col j][row r] (reuse sXnT buffer) ----
    #pragma unroll
    for (int jp = 0; jp < 4; jp++) {
        float2 z0 = unpack2(acc[0][jp]);
        float2 z1 = unpack2(acc[1][jp]);
        float2 z2 = unpack2(acc[2][jp]);
        float2 z3 = unpack2(acc[3][jp]);
        float4 qlo, qhi;
        qlo.x = qlookup(z0.x, sBnd, sCb); qlo.y = qlookup(z1.x, sBnd, sCb);
        qlo.z = qlookup(z2.x, sBnd, sCb); qlo.w = qlookup(z3.x, sBnd, sCb);
        qhi.x = qlookup(z0.y, sBnd, sCb); qhi.y = qlookup(z1.y, sBnd, sCb);
        qhi.z = qlookup(z2.y, sBnd, sCb); qhi.w = qlookup(z3.y, sBnd, sCb);
        *(float4*)(sXnT + (ca + 2 * jp + 0) * LDA + ra) = qlo;   // lanes 16B apart: conflict-free
        *(float4*)(sXnT + (ca + 2 * jp + 1) * LDA + ra) = qhi;
        acc[0][jp] = 0ull; acc[1][jp] = 0ull; acc[2][jp] = 0ull; acc[3][jp] = 0ull;
    }
    __syncthreads();

    // ---- GEMM2: y[r][k] = sum_j zh[r][j] * R[j][k]  (A = ZhT[j][r] smem, B = R[j][k] const) ----
    #pragma unroll 8
    for (int p = 0; p < 64; ++p) {
        float4 a4 = *(const float4*)(sXnT + p * LDA + ra);
        ulonglong2 b01 = *(const ulonglong2*)(cR + p * 64 + ca);
        ulonglong2 b23 = *(const ulonglong2*)(cR + p * 64 + ca + 4);
        ull A0 = pack2dup(a4.x);
        ull A1 = pack2dup(a4.y);
        ull A2 = pack2dup(a4.z);
        ull A3 = pack2dup(a4.w);
        ffma2(acc[0][0], A0, b01.x); ffma2(acc[0][1], A0, b01.y); ffma2(acc[0][2], A0, b23.x); ffma2(acc[0][3], A0, b23.y);
        ffma2(acc[1][0], A1, b01.x); ffma2(acc[1][1], A1, b01.y); ffma2(acc[1][2], A1, b23.x); ffma2(acc[1][3], A1, b23.y);
        ffma2(acc[2][0], A2, b01.x); ffma2(acc[2][1], A2, b01.y); ffma2(acc[2][2], A2, b23.x); ffma2(acc[2][3], A2, b23.y);
        ffma2(acc[3][0], A3, b01.x); ffma2(acc[3][1], A3, b01.y); ffma2(acc[3][2], A3, b23.x); ffma2(acc[3][3], A3, b23.y);
    }

    // ---- rescale and store: each thread rows ra..ra+3, cols ca..ca+7 (32B-aligned) ----
    #pragma unroll
    for (int r = 0; r < 4; r++) {
        long long grow = (long long)row0 + ra + r;
        if (grow >= nrows) break;
        float s = sScale[ra + r];
        float2 y0 = unpack2(acc[r][0]);
        float2 y1 = unpack2(acc[r][1]);
        float2 y2 = unpack2(acc[r][2]);
        float2 y3 = unpack2(acc[r][3]);
        float4 o0, o1;
        o0.x = y0.x * s; o0.y = y0.y * s; o0.z = y1.x * s; o0.w = y1.y * s;
        o1.x = y2.x * s; o1.y = y2.y * s; o1.z = y3.x * s; o1.w = y3.y * s;
        float* op = out + grow * 64 + ca;
        *(float4*)(op)     = o0;
        *(float4*)(op + 4) = o1;
    }
}

extern "C" void kernel_launch(void* const* d_in, const int* in_sizes, int n_in,
                              void* d_out, int out_size)
{
    const float* x  = (const float*)d_in[0];   // [2,32,4096,64] fp32
    const float* cb = (const float*)d_in[1];   // [16] fp32, sorted
    const float* Rg = (const float*)d_in[2];   // [64,64] fp32
    float* out = (float*)d_out;

    int nrows = in_sizes[0] / TDIM;
    int blocks = (nrows + TILE - 1) / TILE;

    // Stage R -> constant, and build+stage RT -> constant (all async, graph-capturable)
    tq_transpose<<<16, 256>>>(Rg);
    cudaMemcpyToSymbolAsync(cR, Rg, 4096 * sizeof(float), 0, cudaMemcpyDeviceToDevice);
    void* rt_dev = nullptr;
    cudaGetSymbolAddress(&rt_dev, g_RT);   // host-side query, not an allocation
    cudaMemcpyToSymbolAsync(cRT, rt_dev, 4096 * sizeof(float), 0, cudaMemcpyDeviceToDevice);

    const int smem_bytes = (64 * LDA + TILE + 32) * (int)sizeof(float);
    cudaFuncSetAttribute(tq_kernel, cudaFuncAttributeMaxDynamicSharedMemorySize, smem_bytes);
    tq_kernel<<<blocks, 256, smem_bytes>>>(x, cb, out, nrows);
}

// round 5
// speedup vs baseline: 1.3694x; 1.3694x over previous
#include <cuda_runtime.h>

#define TDIM 64
#define TILE 256
#define NT   256
#define LDA  260   // stride for XnT/ZhT rows of 256 + pad; 260*4 % 16 == 0
#define LDB  68

typedef unsigned long long ull;

static __device__ __forceinline__ ull pack2dup(float v) {
    ull r; asm("mov.b64 %0, {%1, %1};" : "=l"(r) : "f"(v)); return r;
}
static __device__ __forceinline__ float2 unpack2(ull v) {
    float2 r; asm("mov.b64 {%0, %1}, %2;" : "=f"(r.x), "=f"(r.y) : "l"(v)); return r;
}
// packed fp32x2 FMA, rn — bit-identical to 2x scalar FFMA
static __device__ __forceinline__ void ffma2(ull& d, ull a, ull b) {
    asm("fma.rn.f32x2 %0, %1, %2, %0;" : "+l"(d) : "l"(a), "l"(b));
}

// branchless 4-step binary search over 15 sorted midpoints -> nearest codebook value
static __device__ __forceinline__ float qlookup(float z, const float* __restrict__ sBnd,
                                                const float* __restrict__ sCb) {
    int idx = (z > sBnd[7]) ? 8 : 0;
    idx += (z > sBnd[idx + 3]) ? 4 : 0;
    idx += (z > sBnd[idx + 1]) ? 2 : 0;
    idx += (z > sBnd[idx]) ? 1 : 0;
    return sCb[idx];
}

__global__ void __launch_bounds__(NT, 2)
tq_kernel(const float* __restrict__ x, const float* __restrict__ cb,
          const float* __restrict__ Rg, float* __restrict__ out, int nrows)
{
    extern __shared__ float smem[];
    float* sA     = smem;                  // [64][LDA] XnT k-major; reused as ZhT[j][row]
    float* sRT    = sA + 64 * LDA;         // [64][LDB]  RT[k][j]
    float* sR     = sRT + 64 * LDB;        // [64][LDB]  R[j][k]
    float* sScale = sR + 64 * LDB;         // [TILE]
    float* sCb    = sScale + TILE;         // [16]
    float* sBnd   = sCb + 16;              // [15]

    const int t = threadIdx.x;
    const long long row0 = (long long)blockIdx.x * TILE;

    // ---- stage R and R^T ----
    #pragma unroll
    for (int i = t; i < 64 * 64; i += NT) {
        int j = i >> 6, k = i & 63;
        float v = Rg[i];
        sR[j * LDB + k]  = v;
        sRT[k * LDB + j] = v;
    }
    if (t < 16) sCb[t] = cb[t];
    if (t < 15) sBnd[t] = 0.5f * (cb[t] + cb[t + 1]);

    // ---- prologue: 2 passes, 2 threads per row, per-row norm, write normalized transposed ----
    #pragma unroll
    for (int pass = 0; pass < 2; ++pass) {
        int r = pass * 128 + (t >> 1);   // local row 0..255
        int h = t & 1;                   // which half of the 64 dims
        long long grow = row0 + r;
        long long gr = grow < nrows ? grow : (long long)nrows - 1;
        const float4* xp = (const float4*)(x + gr * 64 + h * 32);
        float4 v[8];
        float ss = 0.f;
        #pragma unroll
        for (int i2 = 0; i2 < 8; i2++) {
            v[i2] = xp[i2];
            ss += v[i2].x * v[i2].x + v[i2].y * v[i2].y + v[i2].z * v[i2].z + v[i2].w * v[i2].w;
        }
        ss += __shfl_xor_sync(0xffffffffu, ss, 1);
        float scale = fmaxf(sqrtf(ss), 1e-8f);
        float inv = 1.0f / scale;   // precise division: fp32-accurate z for the argmin
        if (h == 0) sScale[r] = scale;
        #pragma unroll
        for (int i2 = 0; i2 < 8; i2++) {
            int k = h * 32 + i2 * 4;
            sA[(k + 0) * LDA + r] = v[i2].x * inv;
            sA[(k + 1) * LDA + r] = v[i2].y * inv;
            sA[(k + 2) * LDA + r] = v[i2].z * inv;
            sA[(k + 3) * LDA + r] = v[i2].w * inv;
        }
    }
    __syncthreads();

    // ---- mapping: warp -> 8 cols (B warp-uniform), lane -> 8 rows ----
    const int w  = t >> 5;
    const int l  = t & 31;
    const int ca = 8 * w;     // cols ca..ca+7
    const int ra = 8 * l;     // rows ra..ra+7

    ull acc[4][8];   // [row-pair rp][col c]; f32x2 = rows (ra+2rp, ra+2rp+1), col ca+c
    #pragma unroll
    for (int i = 0; i < 4; i++)
        #pragma unroll
        for (int c = 0; c < 8; c++) acc[i][c] = 0ull;

    // ---- GEMM1: z[r][j] = sum_k xn[r][k] * R[j][k]   (A = XnT, B = RT) ----
    #pragma unroll 8
    for (int p = 0; p < 64; ++p) {
        ulonglong2 a01 = *(const ulonglong2*)(sA + p * LDA + ra);       // rows ra..ra+3
        ulonglong2 a23 = *(const ulonglong2*)(sA + p * LDA + ra + 4);   // rows ra+4..ra+7
        float4 b0 = *(const float4*)(sRT + p * LDB + ca);
        float4 b1 = *(const float4*)(sRT + p * LDB + ca + 4);
        ull A[4] = { a01.x, a01.y, a23.x, a23.y };
        ull B[8] = { pack2dup(b0.x), pack2dup(b0.y), pack2dup(b0.z), pack2dup(b0.w),
                     pack2dup(b1.x), pack2dup(b1.y), pack2dup(b1.z), pack2dup(b1.w) };
        #pragma unroll
        for (int i = 0; i < 4; i++)
            #pragma unroll
            for (int c = 0; c < 8; c++) ffma2(acc[i][c], A[i], B[c]);
    }
    __syncthreads();   // all reads of sA done before overwrite with ZhT

    // ---- quantize, write z_hat transposed into sA: ZhT[col j][rows ra..ra+7] ----
    #pragma unroll
    for (int c = 0; c < 8; c++) {
        float2 z0 = unpack2(acc[0][c]);
        float2 z1 = unpack2(acc[1][c]);
        float2 z2 = unpack2(acc[2][c]);
        float2 z3 = unpack2(acc[3][c]);
        float4 qlo, qhi;
        qlo.x = qlookup(z0.x, sBnd, sCb); qlo.y = qlookup(z0.y, sBnd, sCb);
        qlo.z = qlookup(z1.x, sBnd, sCb); qlo.w = qlookup(z1.y, sBnd, sCb);
        qhi.x = qlookup(z2.x, sBnd, sCb); qhi.y = qlookup(z2.y, sBnd, sCb);
        qhi.z = qlookup(z3.x, sBnd, sCb); qhi.w = qlookup(z3.y, sBnd, sCb);
        float* zp = sA + (ca + c) * LDA + ra;
        *(float4*)(zp)     = qlo;    // lanes 32B apart: conflict-free
        *(float4*)(zp + 4) = qhi;
        acc[0][c] = 0ull; acc[1][c] = 0ull; acc[2][c] = 0ull; acc[3][c] = 0ull;
    }
    __syncthreads();

    // ---- GEMM2: y[r][k] = sum_j zh[r][j] * R[j][k]   (A = ZhT, B = R) ----
    #pragma unroll 8
    for (int p = 0; p < 64; ++p) {
        ulonglong2 a01 = *(const ulonglong2*)(sA + p * LDA + ra);
        ulonglong2 a23 = *(const ulonglong2*)(sA + p * LDA + ra + 4);
        float4 b0 = *(const float4*)(sR + p * LDB + ca);
        float4 b1 = *(const float4*)(sR + p * LDB + ca + 4);
        ull A[4] = { a01.x, a01.y, a23.x, a23.y };
        ull B[8] = { pack2dup(b0.x), pack2dup(b0.y), pack2dup(b0.z), pack2dup(b0.w),
                     pack2dup(b1.x), pack2dup(b1.y), pack2dup(b1.z), pack2dup(b1.w) };
        #pragma unroll
        for (int i = 0; i < 4; i++)
            #pragma unroll
            for (int c = 0; c < 8; c++) ffma2(acc[i][c], A[i], B[c]);
    }

    // ---- rescale + store: rows ra..ra+7, cols ca..ca+7 (two float4 per row) ----
    #pragma unroll
    for (int rp = 0; rp < 4; rp++) {
        float2 y0 = unpack2(acc[rp][0]);
        float2 y1 = unpack2(acc[rp][1]);
        float2 y2 = unpack2(acc[rp][2]);
        float2 y3 = unpack2(acc[rp][3]);
        float2 y4 = unpack2(acc[rp][4]);
        float2 y5 = unpack2(acc[rp][5]);
        float2 y6 = unpack2(acc[rp][6]);
        float2 y7 = unpack2(acc[rp][7]);
        int r0 = ra + 2 * rp;
        long long g0 = row0 + r0;
        float s0 = sScale[r0];
        float s1 = sScale[r0 + 1];
        if (g0 < nrows) {
            float4 o0 = make_float4(y0.x*s0, y1.x*s0, y2.x*s0, y3.x*s0);
            float4 o1 = make_float4(y4.x*s0, y5.x*s0, y6.x*s0, y7.x*s0);
            float* op = out + g0 * 64 + ca;
            *(float4*)(op) = o0; *(float4*)(op + 4) = o1;
        }
        if (g0 + 1 < nrows) {
            float4 o0 = make_float4(y0.y*s1, y1.y*s1, y2.y*s1, y3.y*s1);
            float4 o1 = make_float4(y4.y*s1, y5.y*s1, y6.y*s1, y7.y*s1);
            float* op = out + (g0 + 1) * 64 + ca;
            *(float4*)(op) = o0; *(float4*)(op + 4) = o1;
        }
    }
}

extern "C" void kernel_launch(void* const* d_in, const int* in_sizes, int n_in,
                              void* d_out, int out_size)
{
    const float* x  = (const float*)d_in[0];   // [2,32,4096,64] fp32
    const float* cb = (const float*)d_in[1];   // [16] fp32, sorted
    const float* Rg = (const float*)d_in[2];   // [64,64] fp32
    float* out = (float*)d_out;

    int nrows = in_sizes[0] / TDIM;
    int blocks = (nrows + TILE - 1) / TILE;

    const int smem_bytes = (64 * LDA + 2 * 64 * LDB + TILE + 32) * (int)sizeof(float);
    cudaFuncSetAttribute(tq_kernel, cudaFuncAttributeMaxDynamicSharedMemorySize, smem_bytes);
    tq_kernel<<<blocks, NT, smem_bytes>>>(x, cb, Rg, out, nrows);
}

// round 6
// speedup vs baseline: 1.4549x; 1.0624x over previous
#include <cuda_runtime.h>

#define TDIM 64
#define TILE 256
#define NT   256
#define LDA  260   // k-row stride in floats (256 used); 260*4 % 16 == 0
#define LDB  68

typedef unsigned long long ull;

static __device__ __forceinline__ ull pack2dup(float v) {
    ull r; asm("mov.b64 %0, {%1, %1};" : "=l"(r) : "f"(v)); return r;
}
static __device__ __forceinline__ float2 unpack2(ull v) {
    float2 r; asm("mov.b64 {%0, %1}, %2;" : "=f"(r.x), "=f"(r.y) : "l"(v)); return r;
}
// packed fp32x2 FMA, rn — bit-identical to 2x scalar FFMA
static __device__ __forceinline__ void ffma2(ull& d, ull a, ull b) {
    asm("fma.rn.f32x2 %0, %1, %2, %0;" : "+l"(d) : "l"(a), "l"(b));
}

// row r -> permuted float position within a k-row: even 4-groups first, then odd.
// pos(r) = (g&1)*128 + (g>>1)*4 + (r&3),  g = r>>2
static __device__ __forceinline__ int apos(int r) {
    int g = r >> 2;
    return ((g & 1) << 7) + ((g >> 1) << 2) + (r & 3);
}

// branchless 4-step binary search over 15 sorted midpoints -> nearest codebook value
static __device__ __forceinline__ float qlookup(float z, const float* __restrict__ sBnd,
                                                const float* __restrict__ sCb) {
    int idx = (z > sBnd[7]) ? 8 : 0;
    idx += (z > sBnd[idx + 3]) ? 4 : 0;
    idx += (z > sBnd[idx + 1]) ? 2 : 0;
    idx += (z > sBnd[idx]) ? 1 : 0;
    return sCb[idx];
}

__global__ void __launch_bounds__(NT, 2)
tq_kernel(const float* __restrict__ x, const float* __restrict__ cb,
          const float* __restrict__ Rg, float* __restrict__ out, int nrows)
{
    extern __shared__ float smem[];
    float* sA     = smem;                  // [64][LDA] XnT k-major, row-permuted; reused as ZhT
    float* sRT    = sA + 64 * LDA;         // [64][LDB]  RT[k][j]
    float* sR     = sRT + 64 * LDB;        // [64][LDB]  R[j][k]
    float* sScale = sR + 64 * LDB;         // [TILE]
    float* sCb    = sScale + TILE;         // [16]
    float* sBnd   = sCb + 16;              // [15]

    const int t = threadIdx.x;
    const long long row0 = (long long)blockIdx.x * TILE;

    // ---- stage R and R^T ----
    #pragma unroll
    for (int i = t; i < 64 * 64; i += NT) {
        int j = i >> 6, k = i & 63;
        float v = Rg[i];
        sR[j * LDB + k]  = v;
        sRT[k * LDB + j] = v;
    }
    if (t < 16) sCb[t] = cb[t];
    if (t < 15) sBnd[t] = 0.5f * (cb[t] + cb[t + 1]);

    // ---- prologue: 2 passes, 2 threads per row, per-row norm, write normalized (permuted) ----
    #pragma unroll
    for (int pass = 0; pass < 2; ++pass) {
        int r = pass * 128 + (t >> 1);   // local row 0..255
        int h = t & 1;                   // which half of the 64 dims
        long long grow = row0 + r;
        long long gr = grow < nrows ? grow : (long long)nrows - 1;
        const float4* xp = (const float4*)(x + gr * 64 + h * 32);
        float4 v[8];
        float ss = 0.f;
        #pragma unroll
        for (int i2 = 0; i2 < 8; i2++) {
            v[i2] = xp[i2];
            ss += v[i2].x * v[i2].x + v[i2].y * v[i2].y + v[i2].z * v[i2].z + v[i2].w * v[i2].w;
        }
        ss += __shfl_xor_sync(0xffffffffu, ss, 1);
        float scale = fmaxf(sqrtf(ss), 1e-8f);
        float inv = 1.0f / scale;   // precise division: fp32-accurate z for the argmin
        if (h == 0) sScale[r] = scale;
        const int pr = apos(r);
        #pragma unroll
        for (int i2 = 0; i2 < 8; i2++) {
            int k = h * 32 + i2 * 4;
            sA[(k + 0) * LDA + pr] = v[i2].x * inv;
            sA[(k + 1) * LDA + pr] = v[i2].y * inv;
            sA[(k + 2) * LDA + pr] = v[i2].z * inv;
            sA[(k + 3) * LDA + pr] = v[i2].w * inv;
        }
    }
    __syncthreads();

    // ---- mapping: warp -> 8 cols (B warp-uniform), lane -> 8 rows (rows 8l..8l+7) ----
    const int w  = t >> 5;
    const int l  = t & 31;
    const int ca = 8 * w;     // cols ca..ca+7
    const int ra = 8 * l;     // rows ra..ra+7
    const int aoffE = 4 * l;         // even group 2l  = rows ra..ra+3
    const int aoffO = 128 + 4 * l;   // odd group 2l+1 = rows ra+4..ra+7

    ull acc[4][8];   // [row-pair rp][col c]
    #pragma unroll
    for (int i = 0; i < 4; i++)
        #pragma unroll
        for (int c = 0; c < 8; c++) acc[i][c] = 0ull;

    // ---- GEMM1: z[r][j] = sum_k xn[r][k] * R[j][k]   (A = XnT, B = RT) ----
    #pragma unroll 8
    for (int p = 0; p < 64; ++p) {
        const float* ab = sA + p * LDA;
        ulonglong2 a01 = *(const ulonglong2*)(ab + aoffE);   // rows ra..ra+3   (conflict-free)
        ulonglong2 a23 = *(const ulonglong2*)(ab + aoffO);   // rows ra+4..ra+7 (conflict-free)
        float4 b0 = *(const float4*)(sRT + p * LDB + ca);
        float4 b1 = *(const float4*)(sRT + p * LDB + ca + 4);
        ull A[4] = { a01.x, a01.y, a23.x, a23.y };
        ull B[8] = { pack2dup(b0.x), pack2dup(b0.y), pack2dup(b0.z), pack2dup(b0.w),
                     pack2dup(b1.x), pack2dup(b1.y), pack2dup(b1.z), pack2dup(b1.w) };
        #pragma unroll
        for (int i = 0; i < 4; i++)
            #pragma unroll
            for (int c = 0; c < 8; c++) ffma2(acc[i][c], A[i], B[c]);
    }
    __syncthreads();   // all reads of sA done before overwrite with ZhT

    // ---- quantize, write z_hat transposed into sA (same permuted layout) ----
    #pragma unroll
    for (int c = 0; c < 8; c++) {
        float2 z0 = unpack2(acc[0][c]);
        float2 z1 = unpack2(acc[1][c]);
        float2 z2 = unpack2(acc[2][c]);
        float2 z3 = unpack2(acc[3][c]);
        float4 qlo, qhi;
        qlo.x = qlookup(z0.x, sBnd, sCb); qlo.y = qlookup(z0.y, sBnd, sCb);
        qlo.z = qlookup(z1.x, sBnd, sCb); qlo.w = qlookup(z1.y, sBnd, sCb);
        qhi.x = qlookup(z2.x, sBnd, sCb); qhi.y = qlookup(z2.y, sBnd, sCb);
        qhi.z = qlookup(z3.x, sBnd, sCb); qhi.w = qlookup(z3.y, sBnd, sCb);
        float* zp = sA + (ca + c) * LDA;
        *(float4*)(zp + aoffE) = qlo;   // conflict-free STS.128
        *(float4*)(zp + aoffO) = qhi;
        acc[0][c] = 0ull; acc[1][c] = 0ull; acc[2][c] = 0ull; acc[3][c] = 0ull;
    }
    __syncthreads();

    // ---- GEMM2: y[r][k] = sum_j zh[r][j] * R[j][k]   (A = ZhT, B = R) ----
    #pragma unroll 8
    for (int p = 0; p < 64; ++p) {
        const float* ab = sA + p * LDA;
        ulonglong2 a01 = *(const ulonglong2*)(ab + aoffE);
        ulonglong2 a23 = *(const ulonglong2*)(ab + aoffO);
        float4 b0 = *(const float4*)(sR + p * LDB + ca);
        float4 b1 = *(const float4*)(sR + p * LDB + ca + 4);
        ull A[4] = { a01.x, a01.y, a23.x, a23.y };
        ull B[8] = { pack2dup(b0.x), pack2dup(b0.y), pack2dup(b0.z), pack2dup(b0.w),
                     pack2dup(b1.x), pack2dup(b1.y), pack2dup(b1.z), pack2dup(b1.w) };
        #pragma unroll
        for (int i = 0; i < 4; i++)
            #pragma unroll
            for (int c = 0; c < 8; c++) ffma2(acc[i][c], A[i], B[c]);
    }

    // ---- rescale + store: rows ra..ra+7, cols ca..ca+7 (two float4 per row) ----
    #pragma unroll
    for (int rp = 0; rp < 4; rp++) {
        float2 y0 = unpack2(acc[rp][0]);
        float2 y1 = unpack2(acc[rp][1]);
        float2 y2 = unpack2(acc[rp][2]);
        float2 y3 = unpack2(acc[rp][3]);
        float2 y4 = unpack2(acc[rp][4]);
        float2 y5 = unpack2(acc[rp][5]);
        float2 y6 = unpack2(acc[rp][6]);
        float2 y7 = unpack2(acc[rp][7]);
        int r0 = ra + 2 * rp;
        long long g0 = row0 + r0;
        float s0 = sScale[r0];
        float s1 = sScale[r0 + 1];
        if (g0 < nrows) {
            float4 o0 = make_float4(y0.x*s0, y1.x*s0, y2.x*s0, y3.x*s0);
            float4 o1 = make_float4(y4.x*s0, y5.x*s0, y6.x*s0, y7.x*s0);
            float* op = out + g0 * 64 + ca;
            *(float4*)(op) = o0; *(float4*)(op + 4) = o1;
        }
        if (g0 + 1 < nrows) {
            float4 o0 = make_float4(y0.y*s1, y1.y*s1, y2.y*s1, y3.y*s1);
            float4 o1 = make_float4(y4.y*s1, y5.y*s1, y6.y*s1, y7.y*s1);
            float* op = out + (g0 + 1) * 64 + ca;
            *(float4*)(op) = o0; *(float4*)(op + 4) = o1;
        }
    }
}

extern "C" void kernel_launch(void* const* d_in, const int* in_sizes, int n_in,
                              void* d_out, int out_size)
{
    const float* x  = (const float*)d_in[0];   // [2,32,4096,64] fp32
    const float* cb = (const float*)d_in[1];   // [16] fp32, sorted
    const float* Rg = (const float*)d_in[2];   // [64,64] fp32
    float* out = (float*)d_out;

    int nrows = in_sizes[0] / TDIM;
    int blocks = (nrows + TILE - 1) / TILE;

    const int smem_bytes = (64 * LDA + 2 * 64 * LDB + TILE + 32) * (int)sizeof(float);
    cudaFuncSetAttribute(tq_kernel, cudaFuncAttributeMaxDynamicSharedMemorySize, smem_bytes);
    tq_kernel<<<blocks, NT, smem_bytes>>>(x, cb, Rg, out, nrows);
}

// round 8
// speedup vs baseline: 2.0487x; 1.4081x over previous
#include <cuda_runtime.h>
#include <cuda_fp16.h>
#include <cstdint>

#define TILE 128
#define NT   256

// smem byte offsets (fp16 tiles have 128-byte rows, SW128 swizzle)
#define S_XH   0        // xn hi  fp16 [128][64]
#define S_XL   16384    // xn lo*2048 fp16 [128][64]
#define S_BH   32768    // R[j][k] hi fp16 [n=j][k]   (GEMM1 B)
#define S_BL   40960    // (R-hi)*2048 fp16 [n=j][k]
#define S_RT   49152    // R^T hi fp16 [n=kout][j]    (GEMM2 B)
#define S_E    57344    // E fp16 [128][64]
#define S_SCALE 73728   // float[128]
#define S_CB    74240   // float[16]
#define S_BND   74304   // float[16]
#define SMEM_BYTES 74496

#define INV2048 4.8828125e-4f

// byte offset of fp16 element (row, col) in a [*][64] fp16 tile, SW128 swizzle
static __device__ __forceinline__ int sw(int row, int col) {
    int b = col * 2;
    return row * 128 + (b ^ ((row & 7) << 4));
}

static __device__ __forceinline__ void mma16816(float* c, const uint32_t* a,
                                                uint32_t b0, uint32_t b1) {
    asm volatile("mma.sync.aligned.m16n8k16.row.col.f32.f16.f16.f32 "
        "{%0,%1,%2,%3}, {%4,%5,%6,%7}, {%8,%9}, {%0,%1,%2,%3};"
        : "+f"(c[0]), "+f"(c[1]), "+f"(c[2]), "+f"(c[3])
        : "r"(a[0]), "r"(a[1]), "r"(a[2]), "r"(a[3]), "r"(b0), "r"(b1));
}

// branchless 4-step binary search over 15 sorted midpoints
static __device__ __forceinline__ float qlookup(float z, const float* sBnd, const float* sCb) {
    int idx = (z > sBnd[7]) ? 8 : 0;
    idx += (z > sBnd[idx + 3]) ? 4 : 0;
    idx += (z > sBnd[idx + 1]) ? 2 : 0;
    idx += (z > sBnd[idx]) ? 1 : 0;
    return sCb[idx];
}

__global__ void __launch_bounds__(NT, 2)
tq_mma_kernel(const float* __restrict__ x, const float* __restrict__ cb,
              const float* __restrict__ Rg, float* __restrict__ out, int nrows)
{
    extern __shared__ char smem[];
    float* sScale = (float*)(smem + S_SCALE);
    float* sCb    = (float*)(smem + S_CB);
    float* sBnd   = (float*)(smem + S_BND);

    const int t   = threadIdx.x;
    const int wid = t >> 5;
    const int l   = t & 31;
    const long long row0 = (long long)blockIdx.x * TILE;

    // ---- stage R: hi / scaled-lo for GEMM1 B, hi-transpose for GEMM2 B ----
    for (int i = t; i < 4096; i += NT) {
        int j = i >> 6, k = i & 63;
        float v = Rg[i];
        __half hv = __float2half_rn(v);
        __half lv = __float2half_rn((v - __half2float(hv)) * 2048.0f);
        *(__half*)(smem + S_BH + sw(j, k)) = hv;
        *(__half*)(smem + S_BL + sw(j, k)) = lv;
        *(__half*)(smem + S_RT + sw(k, j)) = hv;
    }
    if (t < 16) sCb[t] = cb[t];
    if (t < 15) sBnd[t] = 0.5f * (cb[t] + cb[t + 1]);

    // ---- prologue: 2 threads per row; norm, split hi / scaled-lo into fp16 tiles ----
    {
        int r = t >> 1;          // local row 0..127 (same 16-row block as this warp's GEMM)
        int h = t & 1;
        long long grow = row0 + r;
        long long gr = grow < nrows ? grow : (long long)nrows - 1;
        const float4* xp = (const float4*)(x + gr * 64 + h * 32);
        float xn[32];
        float ss = 0.f;
        #pragma unroll
        for (int i = 0; i < 8; i++) {
            float4 v = xp[i];
            xn[4*i+0] = v.x; xn[4*i+1] = v.y; xn[4*i+2] = v.z; xn[4*i+3] = v.w;
            ss += v.x*v.x + v.y*v.y + v.z*v.z + v.w*v.w;
        }
        ss += __shfl_xor_sync(0xffffffffu, ss, 1);
        float scale = fmaxf(sqrtf(ss), 1e-8f);
        float inv = 1.0f / scale;
        if (h == 0) sScale[r] = scale;
        #pragma unroll
        for (int p = 0; p < 16; p++) {
            float v0 = xn[2*p] * inv, v1 = xn[2*p+1] * inv;
            __half h0 = __float2half_rn(v0), h1 = __float2half_rn(v1);
            __half l0 = __float2half_rn((v0 - __half2float(h0)) * 2048.0f);
            __half l1 = __float2half_rn((v1 - __half2float(h1)) * 2048.0f);
            int k = h * 32 + 2 * p;
            *(__half2*)(smem + S_XH + sw(r, k)) = __halves2half2(h0, h1);
            *(__half2*)(smem + S_XL + sw(r, k)) = __halves2half2(l0, l1);
        }
    }
    __syncthreads();   // the ONLY block-wide sync: everything after is warp-local

    const int g  = l >> 2;       // fragment row group 0..7
    const int tq = l & 3;        // fragment quad col
    const int rowA = wid * 16 + g;

    // ---- GEMM1: z = xn @ R^T, 3-term fp16 split (lo terms scaled x2048 in C2) ----
    float c1[8][4], c2[8][4];
    #pragma unroll
    for (int nt = 0; nt < 8; nt++)
        #pragma unroll
        for (int i = 0; i < 4; i++) { c1[nt][i] = 0.f; c2[nt][i] = 0.f; }

    #pragma unroll
    for (int ch = 0; ch < 4; ch++) {
        int kb = ch * 16;
        uint32_t ah[4], al[4];
        ah[0] = *(const uint32_t*)(smem + S_XH + sw(rowA,     kb + 2*tq));
        ah[1] = *(const uint32_t*)(smem + S_XH + sw(rowA + 8, kb + 2*tq));
        ah[2] = *(const uint32_t*)(smem + S_XH + sw(rowA,     kb + 2*tq + 8));
        ah[3] = *(const uint32_t*)(smem + S_XH + sw(rowA + 8, kb + 2*tq + 8));
        al[0] = *(const uint32_t*)(smem + S_XL + sw(rowA,     kb + 2*tq));
        al[1] = *(const uint32_t*)(smem + S_XL + sw(rowA + 8, kb + 2*tq));
        al[2] = *(const uint32_t*)(smem + S_XL + sw(rowA,     kb + 2*tq + 8));
        al[3] = *(const uint32_t*)(smem + S_XL + sw(rowA + 8, kb + 2*tq + 8));
        #pragma unroll
        for (int nt = 0; nt < 8; nt++) {
            int n0 = nt * 8 + g;
            uint32_t bh0 = *(const uint32_t*)(smem + S_BH + sw(n0, kb + 2*tq));
            uint32_t bh1 = *(const uint32_t*)(smem + S_BH + sw(n0, kb + 2*tq + 8));
            uint32_t bl0 = *(const uint32_t*)(smem + S_BL + sw(n0, kb + 2*tq));
            uint32_t bl1 = *(const uint32_t*)(smem + S_BL + sw(n0, kb + 2*tq + 8));
            mma16816(c1[nt], ah, bh0, bh1);
            mma16816(c2[nt], ah, bl0, bl1);
            mma16816(c2[nt], al, bh0, bh1);
        }
    }

    // ---- quantize: z -> z_hat; write E = z_hat - z (fp16) to warp-local rows of sE ----
    #pragma unroll
    for (int nt = 0; nt < 8; nt++) {
        float z0 = c1[nt][0] + c2[nt][0] * INV2048;
        float z1 = c1[nt][1] + c2[nt][1] * INV2048;
        float z2 = c1[nt][2] + c2[nt][2] * INV2048;
        float z3 = c1[nt][3] + c2[nt][3] * INV2048;
        float e0 = qlookup(z0, sBnd, sCb) - z0;
        float e1 = qlookup(z1, sBnd, sCb) - z1;
        float e2 = qlookup(z2, sBnd, sCb) - z2;
        float e3 = qlookup(z3, sBnd, sCb) - z3;
        int col = nt * 8 + 2 * tq;
        *(__half2*)(smem + S_E + sw(rowA,     col)) = __floats2half2_rn(e0, e1);
        *(__half2*)(smem + S_E + sw(rowA + 8, col)) = __floats2half2_rn(e2, e3);
    }
    __syncwarp();   // E stores visible to all lanes of this warp before fragment reads

    // ---- GEMM2: d = E @ R (single fp16 term; error-feedback absorbs precision) ----
    float d[8][4];
    #pragma unroll
    for (int nt = 0; nt < 8; nt++)
        #pragma unroll
        for (int i = 0; i < 4; i++) d[nt][i] = 0.f;

    #pragma unroll
    for (int ch = 0; ch < 4; ch++) {
        int jb = ch * 16;
        uint32_t ae[4];
        ae[0] = *(const uint32_t*)(smem + S_E + sw(rowA,     jb + 2*tq));
        ae[1] = *(const uint32_t*)(smem + S_E + sw(rowA + 8, jb + 2*tq));
        ae[2] = *(const uint32_t*)(smem + S_E + sw(rowA,     jb + 2*tq + 8));
        ae[3] = *(const uint32_t*)(smem + S_E + sw(rowA + 8, jb + 2*tq + 8));
        #pragma unroll
        for (int nt = 0; nt < 8; nt++) {
            int n0 = nt * 8 + g;
            uint32_t b0 = *(const uint32_t*)(smem + S_RT + sw(n0, jb + 2*tq));
            uint32_t b1 = *(const uint32_t*)(smem + S_RT + sw(n0, jb + 2*tq + 8));
            mma16816(d[nt], ae, b0, b1);
        }
    }

    // ---- epilogue: y = xn + E@R (xn = hi + lo/2048, exact), rescale, store ----
    {
        float s0 = sScale[wid * 16 + g];
        float s1 = sScale[wid * 16 + g + 8];
        long long grow0 = row0 + rowA;
        long long grow1 = grow0 + 8;
        #pragma unroll
        for (int nt = 0; nt < 8; nt++) {
            int col = nt * 8 + 2 * tq;
            __half2 xh0 = *(const __half2*)(smem + S_XH + sw(rowA, col));
            __half2 xl0 = *(const __half2*)(smem + S_XL + sw(rowA, col));
            __half2 xh1 = *(const __half2*)(smem + S_XH + sw(rowA + 8, col));
            __half2 xl1 = *(const __half2*)(smem + S_XL + sw(rowA + 8, col));
            float2 h0 = __half22float2(xh0), l0f = __half22float2(xl0);
            float2 h1 = __half22float2(xh1), l1f = __half22float2(xl1);
            if (grow0 < nrows) {
                float2 o;
                o.x = (h0.x + l0f.x * INV2048 + d[nt][0]) * s0;
                o.y = (h0.y + l0f.y * INV2048 + d[nt][1]) * s0;
                *(float2*)(out + grow0 * 64 + col) = o;
            }
            if (grow1 < nrows) {
                float2 o;
                o.x = (h1.x + l1f.x * INV2048 + d[nt][2]) * s1;
                o.y = (h1.y + l1f.y * INV2048 + d[nt][3]) * s1;
                *(float2*)(out + grow1 * 64 + col) = o;
            }
        }
    }
}

extern "C" void kernel_launch(void* const* d_in, const int* in_sizes, int n_in,
                              void* d_out, int out_size)
{
    const float* x  = (const float*)d_in[0];   // [2,32,4096,64] fp32
    const float* cb = (const float*)d_in[1];   // [16] fp32, sorted
    const float* Rg = (const float*)d_in[2];   // [64,64] fp32
    float* out = (float*)d_out;

    int nrows = in_sizes[0] / 64;
    int blocks = (nrows + TILE - 1) / TILE;

    cudaFuncSetAttribute(tq_mma_kernel, cudaFuncAttributeMaxDynamicSharedMemorySize, SMEM_BYTES);
    tq_mma_kernel<<<blocks, NT, SMEM_BYTES>>>(x, cb, Rg, out, nrows);
}

// round 9
// speedup vs baseline: 2.9023x; 1.4167x over previous
#include <cuda_runtime.h>
#include <cuda_fp16.h>
#include <cstdint>

#define TILE 128
#define NT   256

// smem layout (bytes). B tiles: 64 rows x 128 B, SW128 swizzle.
#define S_BH   0        // R[j][k] hi fp16      (GEMM1 B)
#define S_BL   8192     // (R - hi)*2048 fp16   (GEMM1 B lo)
#define S_RT   16384    // R^T hi fp16 [kout][j] (GEMM2 B)
#define S_CB   24576    // float[16]
#define S_BND  24640    // float[15]
#define SMEM_BYTES 24704

#define INV2048 4.8828125e-4f

static __device__ __forceinline__ uint32_t smem_u32(const void* p) {
    uint32_t a;
    asm("{ .reg .u64 t; cvta.to.shared.u64 t, %1; cvt.u32.u64 %0, t; }" : "=r"(a) : "l"(p));
    return a;
}
// byte offset of fp16 (row, col) in a [*][64] fp16 tile with SW128 swizzle
static __device__ __forceinline__ int sw(int row, int col) {
    return row * 128 + ((col * 2) ^ ((row & 7) << 4));
}
static __device__ __forceinline__ uint32_t h2u(__half2 h) {
    return *reinterpret_cast<uint32_t*>(&h);
}
static __device__ __forceinline__ void ldsm4(uint32_t* r, uint32_t addr) {
    asm volatile("ldmatrix.sync.aligned.m8n8.x4.shared.b16 {%0,%1,%2,%3}, [%4];"
        : "=r"(r[0]), "=r"(r[1]), "=r"(r[2]), "=r"(r[3]) : "r"(addr));
}
static __device__ __forceinline__ void mma16816(float* c, const uint32_t* a,
                                                uint32_t b0, uint32_t b1) {
    asm volatile("mma.sync.aligned.m16n8k16.row.col.f32.f16.f16.f32 "
        "{%0,%1,%2,%3}, {%4,%5,%6,%7}, {%8,%9}, {%0,%1,%2,%3};"
        : "+f"(c[0]), "+f"(c[1]), "+f"(c[2]), "+f"(c[3])
        : "r"(a[0]), "r"(a[1]), "r"(a[2]), "r"(a[3]), "r"(b0), "r"(b1));
}

__global__ void __launch_bounds__(NT, 2)
tq_mma_kernel(const float* __restrict__ x, const float* __restrict__ cb,
              const float* __restrict__ Rg, float* __restrict__ out, int nrows)
{
    extern __shared__ char smem[];
    const uint32_t sb = smem_u32(smem);
    float* sCb  = (float*)(smem + S_CB);
    float* sBnd = (float*)(smem + S_BND);

    const int t   = threadIdx.x;
    const int wid = t >> 5;
    const int l   = t & 31;
    const int g   = l >> 2;      // fragment row group 0..7
    const int tq  = l & 3;       // fragment quad col
    const long long row0 = (long long)blockIdx.x * TILE;

    // ---- stage R: hi / scaled-lo (GEMM1 B), hi-transpose (GEMM2 B) ----
    #pragma unroll 4
    for (int i = t; i < 4096; i += NT) {
        int j = i >> 6, k = i & 63;
        float v = Rg[i];
        __half hv = __float2half_rn(v);
        __half lv = __float2half_rn((v - __half2float(hv)) * 2048.0f);
        *(__half*)(smem + S_BH + sw(j, k)) = hv;
        *(__half*)(smem + S_BL + sw(j, k)) = lv;
        *(__half*)(smem + S_RT + sw(k, j)) = hv;
    }
    if (t < 16) sCb[t] = cb[t];
    if (t < 15) sBnd[t] = 0.5f * (cb[t] + cb[t + 1]);

    // ---- load x directly in fragment layout: rows rowA, rowA+8; cols {8m+2tq} ----
    const int rowA = wid * 16 + g;
    long long grow0 = row0 + rowA;
    long long grow1 = grow0 + 8;
    long long gr0 = grow0 < nrows ? grow0 : (long long)nrows - 1;
    long long gr1 = grow1 < nrows ? grow1 : (long long)nrows - 1;

    float2 v0[8], v1[8];
    float ss0 = 0.f, ss1 = 0.f;
    #pragma unroll
    for (int m = 0; m < 8; m++) {
        v0[m] = *(const float2*)(x + gr0 * 64 + 8 * m + 2 * tq);
        v1[m] = *(const float2*)(x + gr1 * 64 + 8 * m + 2 * tq);
        ss0 += v0[m].x * v0[m].x + v0[m].y * v0[m].y;
        ss1 += v1[m].x * v1[m].x + v1[m].y * v1[m].y;
    }
    // reduce over the 4 tq-lanes of this g-group
    ss0 += __shfl_xor_sync(0xffffffffu, ss0, 1);
    ss0 += __shfl_xor_sync(0xffffffffu, ss0, 2);
    ss1 += __shfl_xor_sync(0xffffffffu, ss1, 1);
    ss1 += __shfl_xor_sync(0xffffffffu, ss1, 2);
    float scale0 = fmaxf(sqrtf(ss0), 1e-8f);
    float scale1 = fmaxf(sqrtf(ss1), 1e-8f);
    float inv0 = 1.0f / scale0;
    float inv1 = 1.0f / scale1;

    // split hi / scaled-lo into half2 registers (fragment order: m = k-block)
    uint32_t xh0[8], xl0[8], xh1[8], xl1[8];
    #pragma unroll
    for (int m = 0; m < 8; m++) {
        float a0 = v0[m].x * inv0, a1 = v0[m].y * inv0;
        float b0 = v1[m].x * inv1, b1 = v1[m].y * inv1;
        __half2 h0 = __floats2half2_rn(a0, a1);
        __half2 h1 = __floats2half2_rn(b0, b1);
        float2 hf0 = __half22float2(h0), hf1 = __half22float2(h1);
        xh0[m] = h2u(h0);
        xh1[m] = h2u(h1);
        xl0[m] = h2u(__floats2half2_rn((a0 - hf0.x) * 2048.0f, (a1 - hf0.y) * 2048.0f));
        xl1[m] = h2u(__floats2half2_rn((b0 - hf1.x) * 2048.0f, (b1 - hf1.y) * 2048.0f));
    }
    __syncthreads();   // B tiles + cb/bnd ready

    // boundary registers for the quantizer select tree
    const float m1 = sBnd[1], m3 = sBnd[3], m5 = sBnd[5], m7 = sBnd[7];
    const float m9 = sBnd[9], m11 = sBnd[11], m13 = sBnd[13];

    // ---- LDSM lane addressing (shared by all three B tiles) ----
    const int tl  = l >> 3;                 // tile index 0..3
    const int rwi = l & 7;                  // row within 8-row tile
    const int rsel = ((tl & 2) << 2) + rwi; // row within 16-row ntp block
    const int cbyte = (tl & 1) << 4;        // k-block byte offset (0 / 16)
    const int swz = rwi << 4;
    int lo[4];
    #pragma unroll
    for (int ch = 0; ch < 4; ch++) lo[ch] = rsel * 128 + ((ch * 32 + cbyte) ^ swz);

    // ---- GEMM1: z = xn @ R^T, 3-term fp16 split ----
    float c1[8][4], c2[8][4];
    #pragma unroll
    for (int nt = 0; nt < 8; nt++)
        #pragma unroll
        for (int i = 0; i < 4; i++) { c1[nt][i] = 0.f; c2[nt][i] = 0.f; }

    #pragma unroll
    for (int ch = 0; ch < 4; ch++) {
        uint32_t ah[4] = { xh0[2*ch], xh1[2*ch], xh0[2*ch+1], xh1[2*ch+1] };
        uint32_t al[4] = { xl0[2*ch], xl1[2*ch], xl0[2*ch+1], xl1[2*ch+1] };
        #pragma unroll
        for (int ntp = 0; ntp < 4; ntp++) {
            uint32_t bh[4], bl[4];
            ldsm4(bh, sb + S_BH + ntp * 2048 + lo[ch]);
            ldsm4(bl, sb + S_BL + ntp * 2048 + lo[ch]);
            mma16816(c1[2*ntp],     ah, bh[0], bh[1]);
            mma16816(c2[2*ntp],     ah, bl[0], bl[1]);
            mma16816(c2[2*ntp],     al, bh[0], bh[1]);
            mma16816(c1[2*ntp+1],   ah, bh[2], bh[3]);
            mma16816(c2[2*ntp+1],   ah, bl[2], bl[3]);
            mma16816(c2[2*ntp+1],   al, bh[2], bh[3]);
        }
    }

    // ---- quantize (3 register tree levels + 2 LDS), E kept in registers ----
    uint32_t e01[8], e23[8];
    #pragma unroll
    for (int nt = 0; nt < 8; nt++) {
        float e[4];
        #pragma unroll
        for (int i = 0; i < 4; i++) {
            float z = c1[nt][i] + c2[nt][i] * INV2048;
            bool cA = z > m7;
            float b2 = cA ? m11 : m3;
            bool cB = z > b2;
            float b3 = cA ? (cB ? m13 : m9) : (cB ? m5 : m1);
            bool cC = z > b3;
            int off = (cA ? 32 : 0) + (cB ? 16 : 0) + (cC ? 8 : 0);   // idx*4, idx even
            float b4 = *(const float*)(smem + S_BND + off);
            int voff = off + ((z > b4) ? 4 : 0);
            float q = *(const float*)(smem + S_CB + voff);
            e[i] = q - z;
            c1[nt][i] = 0.f;   // reuse c1 as GEMM2 accumulator
        }
        e01[nt] = h2u(__floats2half2_rn(e[0], e[1]));
        e23[nt] = h2u(__floats2half2_rn(e[2], e[3]));
    }

    // ---- GEMM2: d = E @ R (A = repacked C fragments; single fp16 term) ----
    #pragma unroll
    for (int ch = 0; ch < 4; ch++) {
        uint32_t ae[4] = { e01[2*ch], e23[2*ch], e01[2*ch+1], e23[2*ch+1] };
        #pragma unroll
        for (int ntp = 0; ntp < 4; ntp++) {
            uint32_t br[4];
            ldsm4(br, sb + S_RT + ntp * 2048 + lo[ch]);
            mma16816(c1[2*ntp],   ae, br[0], br[1]);
            mma16816(c1[2*ntp+1], ae, br[2], br[3]);
        }
    }

    // ---- epilogue: y = xn + E@R, rescale, store from registers ----
    #pragma unroll
    for (int nt = 0; nt < 8; nt++) {
        float2 h0 = __half22float2(*reinterpret_cast<__half2*>(&xh0[nt]));
        float2 l0 = __half22float2(*reinterpret_cast<__half2*>(&xl0[nt]));
        float2 h1 = __half22float2(*reinterpret_cast<__half2*>(&xh1[nt]));
        float2 l1 = __half22float2(*reinterpret_cast<__half2*>(&xl1[nt]));
        int col = 8 * nt + 2 * tq;
        if (grow0 < nrows) {
            float2 o;
            o.x = (h0.x + l0.x * INV2048 + c1[nt][0]) * scale0;
            o.y = (h0.y + l0.y * INV2048 + c1[nt][1]) * scale0;
            *(float2*)(out + grow0 * 64 + col) = o;
        }
        if (grow1 < nrows) {
            float2 o;
            o.x = (h1.x + l1.x * INV2048 + c1[nt][2]) * scale1;
            o.y = (h1.y + l1.y * INV2048 + c1[nt][3]) * scale1;
            *(float2*)(out + grow1 * 64 + col) = o;
        }
    }
}

extern "C" void kernel_launch(void* const* d_in, const int* in_sizes, int n_in,
                              void* d_out, int out_size)
{
    const float* x  = (const float*)d_in[0];   // [2,32,4096,64] fp32
    const float* cb = (const float*)d_in[1];   // [16] fp32, sorted
    const float* Rg = (const float*)d_in[2];   // [64,64] fp32
    float* out = (float*)d_out;

    int nrows = in_sizes[0] / 64;
    int blocks = (nrows + TILE - 1) / TILE;

    tq_mma_kernel<<<blocks, NT, SMEM_BYTES>>>(x, cb, Rg, out, nrows);
}